// round 7
// baseline (speedup 1.0000x reference)
#include <cuda_runtime.h>
#include <cstdint>
#include <cstddef>

#define Mdim 128
#define Ndim 64
#define Edim 32
#define Sdim 512
#define Bdim 8192

typedef unsigned long long ull;

// ---------------- scratch (no allocation allowed) ----------------
__device__ float g_w[Bdim * Edim];   // expert weights: [b*32 + e]

// ---------------- packed f32x2 helpers (sm_103a) ----------------
__device__ __forceinline__ void fma2(ull& acc, ull a, ull b)
{
    asm("fma.rn.f32x2 %0, %1, %2, %3;" : "=l"(acc) : "l"(a), "l"(b), "l"(acc));
}
__device__ __forceinline__ void mul2(ull& a, ull b)
{
    asm("mul.rn.f32x2 %0, %1, %2;" : "=l"(a) : "l"(a), "l"(b));
}
__device__ __forceinline__ ull bcast2(float x)
{
    ull r;
    asm("mov.b64 %0, {%1, %1};" : "=l"(r) : "f"(x));
    return r;
}
__device__ __forceinline__ float2 unpack2(ull v)
{
    float2 f;
    asm("mov.b64 {%0, %1}, %2;" : "=f"(f.x), "=f"(f.y) : "l"(v));
    return f;
}
__device__ __forceinline__ uint32_t smem_addr(const void* p)
{
    return (uint32_t)__cvta_generic_to_shared(p);
}
__device__ __forceinline__ void cp8(uint32_t dst, const void* src)
{
    asm volatile("cp.async.ca.shared.global [%0], [%1], 8;" :: "r"(dst), "l"(src));
}

// ---------------- Kernel 0: zero the output (atomics accumulate into it) ----------------
__global__ void k_zero(float* __restrict__ out)
{
    int idx = blockIdx.x * blockDim.x + threadIdx.x;
    reinterpret_cast<float4*>(out)[idx] = make_float4(0.f, 0.f, 0.f, 0.f);
}

// ---------------- Kernel A: fused z_cur + tiled online-softmax attention
// ----------------           + conv-emb + MLP + expert softmax ----------------
#define K2_WARPS 8
#define TROWS 16
#define TSTRIDE 66           // floats per smem tile row (pad for banks, 8B aligned)
#define TILE_FLOATS (TROWS * TSTRIDE)
#define NTILES 32

__global__ __launch_bounds__(256)
void k_attn(const float* __restrict__ ctx, const float* __restrict__ z,
            const float* __restrict__ noise, const float* __restrict__ Dm,
            const float* __restrict__ sigma_g,
            const float* __restrict__ conv_w, const float* __restrict__ conv_b,
            const float* __restrict__ temp1,
            const float* __restrict__ W1, const float* __restrict__ b1,
            const float* __restrict__ W2, const float* __restrict__ b2,
            const float* __restrict__ temp2)
{
    extern __shared__ float tiles[];         // [8 warps][2][TROWS][TSTRIDE]  67.6 KB
    __shared__ float W1s[192 * 32];          // transposed [j][e]   24 KB
    __shared__ float W2s[32 * 32];           // transposed [j][e]    4 KB
    __shared__ float scomb[K2_WARPS][194];   // per-warp work        6.2 KB
    __shared__ float zs[Mdim][8];            // z[m][bb]             4 KB
    __shared__ float zcs[8][66];             // z_cur[bb][i]         2.1 KB

    int tid = threadIdx.x;
    int b0 = blockIdx.x * K2_WARPS;

    // ---- stage z tile [128 x 8] ----
    #pragma unroll
    for (int r = 0; r < 4; ++r) {
        int idx = tid + r * 256;
        int m = idx >> 3, bb = idx & 7;
        zs[m][bb] = z[(size_t)m * Bdim + b0 + bb];
    }
    // ---- stage MLP weights (transposed) ----
    for (int t = tid; t < 192 * 32; t += 256) {
        int e = t / 192, j = t % 192;
        W1s[j * 32 + e] = W1[t];
    }
    for (int t = tid; t < 32 * 32; t += 256) {
        int e = t / 32, j = t % 32;
        W2s[j * 32 + e] = W2[t];
    }
    __syncthreads();

    // ---- fused z_cur: zc[i][bb] = sigma[i]*noise[i,b] + sum_m D[i,m] z[m,b] ----
    {
        int i = tid >> 2;                    // 0..63
        int bb0 = (tid & 3) * 2;             // 0,2,4,6
        float a0 = sigma_g[i] * noise[(size_t)i * Bdim + b0 + bb0];
        float a1 = sigma_g[i] * noise[(size_t)i * Bdim + b0 + bb0 + 1];
        const float* drow = Dm + i * Mdim;
        #pragma unroll 4
        for (int m = 0; m < Mdim; ++m) {
            float d = __ldg(drow + m);
            float2 zz = *reinterpret_cast<const float2*>(&zs[m][bb0]);
            a0 = fmaf(d, zz.x, a0);
            a1 = fmaf(d, zz.y, a1);
        }
        zcs[bb0][i] = a0;
        zcs[bb0 + 1][i] = a1;
    }
    __syncthreads();

    int warp = tid >> 5, lane = tid & 31;
    int b = b0 + warp;

    float invT1 = 1.0f / fabsf(temp1[0]);
    float invT2 = 1.0f / fabsf(temp2[0]);

    int r = lane & 15;                       // row owned in dist phase
    int colbase = (lane >> 4) * 32;          // column half owned

    // zc values for this lane's column half, kept in registers
    float2 zcr[16];
    #pragma unroll
    for (int c = 0; c < 16; ++c)
        zcr[c] = *reinterpret_cast<const float2*>(&zcs[warp][colbase + 2 * c]);

    float* tb = tiles + warp * (2 * TILE_FLOATS);
    uint32_t tb_u32 = smem_addr(tb);
    const float* gbase = ctx + (size_t)b * Ndim;          // + s * Bdim*Ndim
    const size_t SROW = (size_t)Bdim * Ndim;              // floats per s step

    // ---- prologue: issue tiles 0, 1 ----
    #pragma unroll
    for (int t0 = 0; t0 < 2; ++t0) {
        const float* src = gbase + (size_t)t0 * TROWS * SROW + 2 * lane;
        uint32_t dst = tb_u32 + t0 * (TILE_FLOATS * 4) + lane * 8;
        #pragma unroll
        for (int rr = 0; rr < TROWS; ++rr)
            cp8(dst + rr * (TSTRIDE * 4), src + (size_t)rr * SROW);
        asm volatile("cp.async.commit_group;");
    }

    float M = -1e30f, denom = 0.f, pprev = 0.f;
    ull c0 = 0ull, c1 = 0ull;

    for (int t = 0; t < NTILES; ++t) {
        if (t == NTILES - 1) asm volatile("cp.async.wait_group 0;");
        else                 asm volatile("cp.async.wait_group 1;");
        __syncwarp();
        const float* tbuf = tb + (t & 1) * TILE_FLOATS;

        // ---- dist: lane computes half-row, 1 shfl to combine ----
        float dd = 0.f;
        #pragma unroll
        for (int c = 0; c < 16; ++c) {
            float2 x = *reinterpret_cast<const float2*>(&tbuf[r * TSTRIDE + colbase + 2 * c]);
            dd += fabsf(x.x - zcr[c].x);
            dd += fabsf(x.y - zcr[c].y);
        }
        dd += __shfl_xor_sync(0xffffffffu, dd, 16);
        float logit = -dd * invT1;
        if (t == NTILES - 1 && r == TROWS - 1) logit = -1e30f;   // s=511 excluded

        // ---- tile max + online rescale (once per 16 rows) ----
        float mt = logit;
        mt = fmaxf(mt, __shfl_xor_sync(0xffffffffu, mt, 1));
        mt = fmaxf(mt, __shfl_xor_sync(0xffffffffu, mt, 2));
        mt = fmaxf(mt, __shfl_xor_sync(0xffffffffu, mt, 4));
        mt = fmaxf(mt, __shfl_xor_sync(0xffffffffu, mt, 8));
        float Mn = fmaxf(M, mt);
        float scl = __expf(M - Mn);
        M = Mn;
        denom *= scl;
        pprev *= scl;
        ull sp = bcast2(scl);
        mul2(c0, sp);
        mul2(c1, sp);

        float w = __expf(logit - M);         // one MUFU per lane covers its row
        float ws = (lane < 16) ? w : 0.f;
        ws += __shfl_xor_sync(0xffffffffu, ws, 16);
        ws += __shfl_xor_sync(0xffffffffu, ws, 8);
        ws += __shfl_xor_sync(0xffffffffu, ws, 4);
        ws += __shfl_xor_sync(0xffffffffu, ws, 2);
        ws += __shfl_xor_sync(0xffffffffu, ws, 1);
        denom += ws;

        // ---- accumulate: lanes over i-pairs, packed FFMA2 ----
        float wp = pprev;
        #pragma unroll
        for (int r2 = 0; r2 < TROWS; ++r2) {
            float wr = __shfl_sync(0xffffffffu, w, r2);
            ull x = *reinterpret_cast<const ull*>(&tbuf[r2 * TSTRIDE + 2 * lane]);
            fma2(c0, bcast2(wr), x);
            fma2(c1, bcast2(wp), x);
            wp = wr;
        }
        pprev = wp;
        __syncwarp();

        // ---- issue tile t+2 into the buffer just freed ----
        if (t + 2 < NTILES) {
            const float* src = gbase + (size_t)(t + 2) * TROWS * SROW + 2 * lane;
            uint32_t dst = tb_u32 + ((t + 2) & 1) * (TILE_FLOATS * 4) + lane * 8;
            #pragma unroll
            for (int rr = 0; rr < TROWS; ++rr)
                cp8(dst + rr * (TSTRIDE * 4), src + (size_t)rr * SROW);
            asm volatile("cp.async.commit_group;");
        }
    }

    float rinv = 1.0f / denom;
    float* sc = scomb[warp];
    float2 c0u = unpack2(c0);
    float2 c1u = unpack2(c1);
    sc[2 * lane]      = c0u.x * rinv;  sc[2 * lane + 1]      = c0u.y * rinv;
    sc[64 + 2 * lane] = c1u.x * rinv;  sc[64 + 2 * lane + 1] = c1u.y * rinv;
    __syncwarp();

    // emb[o] = conv_b[o] + sum_i cw0[o,i]*c0[i] + cw1[o,i]*c1[i]
    int o0 = 2 * lane, o1 = 2 * lane + 1;
    float e0 = conv_b[o0], e1 = conv_b[o1];
    const float* cwA = conv_w + (size_t)o0 * 128;   // conv_w[o][i][tap]
    const float* cwB = conv_w + (size_t)o1 * 128;
    #pragma unroll 8
    for (int i = 0; i < 64; ++i) {
        float a = sc[i], c = sc[64 + i];
        e0 = fmaf(__ldg(cwA + 2 * i), a, e0);
        e0 = fmaf(__ldg(cwA + 2 * i + 1), c, e0);
        e1 = fmaf(__ldg(cwB + 2 * i), a, e1);
        e1 = fmaf(__ldg(cwB + 2 * i + 1), c, e1);
    }
    __syncwarp();
    sc[o0] = e0; sc[o1] = e1;                      // combined[0..63] = emb
    #pragma unroll
    for (int k = 0; k < 4; ++k) {
        int j = lane * 4 + k;
        sc[64 + j] = zs[j][warp];                  // combined[64..191] = z[:,b]
    }
    __syncwarp();

    // hidden[e] = relu(W1[e,:] . combined + b1[e]), lane == e
    float hs = b1[lane];
    #pragma unroll 8
    for (int j = 0; j < 192; ++j)
        hs = fmaf(W1s[j * 32 + lane], sc[j], hs);
    hs = fmaxf(hs, 0.f);

    float o2 = b2[lane];
    #pragma unroll
    for (int j = 0; j < 32; ++j)
        o2 = fmaf(W2s[j * 32 + lane], __shfl_sync(0xffffffffu, hs, j), o2);

    // expert softmax over lanes
    float lg = -o2 * invT2;
    float mx = lg;
    mx = fmaxf(mx, __shfl_xor_sync(0xffffffffu, mx, 16));
    mx = fmaxf(mx, __shfl_xor_sync(0xffffffffu, mx, 8));
    mx = fmaxf(mx, __shfl_xor_sync(0xffffffffu, mx, 4));
    mx = fmaxf(mx, __shfl_xor_sync(0xffffffffu, mx, 2));
    mx = fmaxf(mx, __shfl_xor_sync(0xffffffffu, mx, 1));
    float pw2 = __expf(lg - mx);
    float sm2 = pw2;
    sm2 += __shfl_xor_sync(0xffffffffu, sm2, 16);
    sm2 += __shfl_xor_sync(0xffffffffu, sm2, 8);
    sm2 += __shfl_xor_sync(0xffffffffu, sm2, 4);
    sm2 += __shfl_xor_sync(0xffffffffu, sm2, 2);
    sm2 += __shfl_xor_sync(0xffffffffu, sm2, 1);
    g_w[(size_t)b * 32 + lane] = pw2 / sm2;
}

// ---------------- Kernel B: MoE mixture GEMM, k-split(4) + FFMA2 ----------------
#define K3_BT 64
#define K3_MT 64
#define K3_THREADS 128
#define K3_SPLITS 4
#define K3_CHUNKS 32            // chunks per k-split (128 total / 4 splits)

__global__ __launch_bounds__(K3_THREADS, 4)
void k_mix(const float* __restrict__ z, const float* __restrict__ Wx,
           const float* __restrict__ Amat, const float* __restrict__ hmat,
           float* __restrict__ out)
{
    __shared__ __align__(16) float Ws[2][32][68];   // [stage][k][m]   17.4 KB
    __shared__ __align__(16) float Vs[2][32][68];   // [stage][k][b]   17.4 KB
    __shared__ __align__(16) float w_s[32][68];     // [e][b]           8.7 KB

    int tid = threadIdx.x;
    int b0 = blockIdx.x * K3_BT;
    int m0 = blockIdx.y * K3_MT;
    int ks = blockIdx.z;
    int tx = tid & 7;
    int ty = tid >> 3;
    int tx8 = tx * 8, ty4 = ty * 4;

    #pragma unroll
    for (int r = 0; r < 16; ++r) {
        int idx = tid + r * K3_THREADS;
        int bb = idx >> 5, e = idx & 31;
        w_s[e][bb] = g_w[(size_t)(b0 + bb) * 32 + e];
    }
    __syncthreads();

    ull acc[4][4];
    #pragma unroll
    for (int i = 0; i < 4; ++i)
        #pragma unroll
        for (int j = 0; j < 4; ++j) acc[i][j] = 0ull;

    float4 rW[4], rV[4];

    {
        int g = ks * K3_CHUNKS;
        int e = g >> 2, k0 = (g & 3) << 5;
        const float* wxb = Wx + (size_t)e * (Mdim * Mdim) + (size_t)m0 * Mdim + k0;
        #pragma unroll
        for (int rr = 0; rr < 4; ++rr) {
            int q = tid + rr * K3_THREADS;
            int mm = q >> 3, kq = q & 7;
            rW[rr] = *reinterpret_cast<const float4*>(wxb + (size_t)mm * Mdim + kq * 4);
        }
        #pragma unroll
        for (int rr = 0; rr < 4; ++rr) {
            int idx = tid + rr * K3_THREADS;
            int kk = idx >> 4, bq = (idx & 15) * 4;
            rV[rr] = *reinterpret_cast<const float4*>(z + (size_t)(k0 + kk) * Bdim + b0 + bq);
        }
        #pragma unroll
        for (int rr = 0; rr < 4; ++rr) {
            int q = tid + rr * K3_THREADS;
            int mm = q >> 3, kq = q & 7;
            Ws[0][kq * 4 + 0][mm] = rW[rr].x;
            Ws[0][kq * 4 + 1][mm] = rW[rr].y;
            Ws[0][kq * 4 + 2][mm] = rW[rr].z;
            Ws[0][kq * 4 + 3][mm] = rW[rr].w;
        }
        #pragma unroll
        for (int rr = 0; rr < 4; ++rr) {
            int idx = tid + rr * K3_THREADS;
            int kk = idx >> 4, bq = (idx & 15) * 4;
            int kg = k0 + kk;
            float4 v = rV[rr];
            if (kg >= Mdim - 2) {
                v.x = fmaxf(v.x, 0.f); v.y = fmaxf(v.y, 0.f);
                v.z = fmaxf(v.z, 0.f); v.w = fmaxf(v.w, 0.f);
            }
            float4 wq = *reinterpret_cast<const float4*>(&w_s[e][bq]);
            v.x *= wq.x; v.y *= wq.y; v.z *= wq.z; v.w *= wq.w;
            *reinterpret_cast<float4*>(&Vs[0][kk][bq]) = v;
        }
    }
    __syncthreads();

    for (int c = 0; c < K3_CHUNKS; ++c) {
        int s = c & 1;
        int en = 0, k0n = 0;
        if (c < K3_CHUNKS - 1) {
            int g = ks * K3_CHUNKS + c + 1;
            en = g >> 2; k0n = (g & 3) << 5;
            const float* wxb = Wx + (size_t)en * (Mdim * Mdim) + (size_t)m0 * Mdim + k0n;
            #pragma unroll
            for (int rr = 0; rr < 4; ++rr) {
                int q = tid + rr * K3_THREADS;
                int mm = q >> 3, kq = q & 7;
                rW[rr] = *reinterpret_cast<const float4*>(wxb + (size_t)mm * Mdim + kq * 4);
            }
            #pragma unroll
            for (int rr = 0; rr < 4; ++rr) {
                int idx = tid + rr * K3_THREADS;
                int kk = idx >> 4, bq = (idx & 15) * 4;
                rV[rr] = *reinterpret_cast<const float4*>(z + (size_t)(k0n + kk) * Bdim + b0 + bq);
            }
        }

        #pragma unroll
        for (int kk = 0; kk < 32; ++kk) {
            float4 wv = *reinterpret_cast<const float4*>(&Ws[s][kk][ty4]);
            ulonglong2 va = *reinterpret_cast<const ulonglong2*>(&Vs[s][kk][tx8]);
            ulonglong2 vb = *reinterpret_cast<const ulonglong2*>(&Vs[s][kk][tx8 + 4]);
            ull w0 = bcast2(wv.x), w1 = bcast2(wv.y), w2 = bcast2(wv.z), w3 = bcast2(wv.w);
            fma2(acc[0][0], w0, va.x); fma2(acc[0][1], w0, va.y);
            fma2(acc[0][2], w0, vb.x); fma2(acc[0][3], w0, vb.y);
            fma2(acc[1][0], w1, va.x); fma2(acc[1][1], w1, va.y);
            fma2(acc[1][2], w1, vb.x); fma2(acc[1][3], w1, vb.y);
            fma2(acc[2][0], w2, va.x); fma2(acc[2][1], w2, va.y);
            fma2(acc[2][2], w2, vb.x); fma2(acc[2][3], w2, vb.y);
            fma2(acc[3][0], w3, va.x); fma2(acc[3][1], w3, va.y);
            fma2(acc[3][2], w3, vb.x); fma2(acc[3][3], w3, vb.y);
        }

        if (c < K3_CHUNKS - 1) {
            int sn = (c + 1) & 1;
            #pragma unroll
            for (int rr = 0; rr < 4; ++rr) {
                int q = tid + rr * K3_THREADS;
                int mm = q >> 3, kq = q & 7;
                Ws[sn][kq * 4 + 0][mm] = rW[rr].x;
                Ws[sn][kq * 4 + 1][mm] = rW[rr].y;
                Ws[sn][kq * 4 + 2][mm] = rW[rr].z;
                Ws[sn][kq * 4 + 3][mm] = rW[rr].w;
            }
            #pragma unroll
            for (int rr = 0; rr < 4; ++rr) {
                int idx = tid + rr * K3_THREADS;
                int kk = idx >> 4, bq = (idx & 15) * 4;
                int kg = k0n + kk;
                float4 v = rV[rr];
                if (kg >= Mdim - 2) {
                    v.x = fmaxf(v.x, 0.f); v.y = fmaxf(v.y, 0.f);
                    v.z = fmaxf(v.z, 0.f); v.w = fmaxf(v.w, 0.f);
                }
                float4 wq = *reinterpret_cast<const float4*>(&w_s[en][bq]);
                v.x *= wq.x; v.y *= wq.y; v.z *= wq.z; v.w *= wq.w;
                *reinterpret_cast<float4*>(&Vs[sn][kk][bq]) = v;
            }
        }
        __syncthreads();
    }

    if (ks == 0) {
        ull aA[4][4];
        #pragma unroll
        for (int i = 0; i < 4; ++i)
            #pragma unroll
            for (int j = 0; j < 4; ++j) aA[i][j] = 0ull;

        #pragma unroll 4
        for (int e = 0; e < 32; ++e) {
            float4 hv = *reinterpret_cast<const float4*>(hmat + (size_t)e * Mdim + m0 + ty4);
            float4 av = *reinterpret_cast<const float4*>(Amat + (size_t)e * Mdim + m0 + ty4);
            ulonglong2 wa = *reinterpret_cast<const ulonglong2*>(&w_s[e][tx8]);
            ulonglong2 wb = *reinterpret_cast<const ulonglong2*>(&w_s[e][tx8 + 4]);
            ull h0 = bcast2(hv.x), h1 = bcast2(hv.y), h2 = bcast2(hv.z), h3 = bcast2(hv.w);
            ull a0 = bcast2(av.x), a1 = bcast2(av.y), a2 = bcast2(av.z), a3 = bcast2(av.w);
            fma2(acc[0][0], h0, wa.x); fma2(acc[0][1], h0, wa.y); fma2(acc[0][2], h0, wb.x); fma2(acc[0][3], h0, wb.y);
            fma2(acc[1][0], h1, wa.x); fma2(acc[1][1], h1, wa.y); fma2(acc[1][2], h1, wb.x); fma2(acc[1][3], h1, wb.y);
            fma2(acc[2][0], h2, wa.x); fma2(acc[2][1], h2, wa.y); fma2(acc[2][2], h2, wb.x); fma2(acc[2][3], h2, wb.y);
            fma2(acc[3][0], h3, wa.x); fma2(acc[3][1], h3, wa.y); fma2(acc[3][2], h3, wb.x); fma2(acc[3][3], h3, wb.y);
            fma2(aA[0][0], a0, wa.x); fma2(aA[0][1], a0, wa.y); fma2(aA[0][2], a0, wb.x); fma2(aA[0][3], a0, wb.y);
            fma2(aA[1][0], a1, wa.x); fma2(aA[1][1], a1, wa.y); fma2(aA[1][2], a1, wb.x); fma2(aA[1][3], a1, wb.y);
            fma2(aA[2][0], a2, wa.x); fma2(aA[2][1], a2, wa.y); fma2(aA[2][2], a2, wb.x); fma2(aA[2][3], a2, wb.y);
            fma2(aA[3][0], a3, wa.x); fma2(aA[3][1], a3, wa.y); fma2(aA[3][2], a3, wb.x); fma2(aA[3][3], a3, wb.y);
        }

        #pragma unroll
        for (int i = 0; i < 4; ++i) {
            int m = m0 + ty4 + i;
            float* op = out + (size_t)m * Bdim + b0 + tx8;
            const float* zp = z + (size_t)m * Bdim + b0 + tx8;
            float4 z0 = *reinterpret_cast<const float4*>(zp);
            float4 z1 = *reinterpret_cast<const float4*>(zp + 4);
            float2 g0 = unpack2(acc[i][0]); float2 g1 = unpack2(acc[i][1]);
            float2 g2 = unpack2(acc[i][2]); float2 g3 = unpack2(acc[i][3]);
            float2 q0 = unpack2(aA[i][0]);  float2 q1 = unpack2(aA[i][1]);
            float2 q2 = unpack2(aA[i][2]);  float2 q3 = unpack2(aA[i][3]);
            atomicAdd(op + 0, fmaf(z0.x, q0.x, g0.x));
            atomicAdd(op + 1, fmaf(z0.y, q0.y, g0.y));
            atomicAdd(op + 2, fmaf(z0.z, q1.x, g1.x));
            atomicAdd(op + 3, fmaf(z0.w, q1.y, g1.y));
            atomicAdd(op + 4, fmaf(z1.x, q2.x, g2.x));
            atomicAdd(op + 5, fmaf(z1.y, q2.y, g2.y));
            atomicAdd(op + 6, fmaf(z1.z, q3.x, g3.x));
            atomicAdd(op + 7, fmaf(z1.w, q3.y, g3.y));
        }
    } else {
        #pragma unroll
        for (int i = 0; i < 4; ++i) {
            int m = m0 + ty4 + i;
            float* op = out + (size_t)m * Bdim + b0 + tx8;
            float2 g0 = unpack2(acc[i][0]); float2 g1 = unpack2(acc[i][1]);
            float2 g2 = unpack2(acc[i][2]); float2 g3 = unpack2(acc[i][3]);
            atomicAdd(op + 0, g0.x);
            atomicAdd(op + 1, g0.y);
            atomicAdd(op + 2, g1.x);
            atomicAdd(op + 3, g1.y);
            atomicAdd(op + 4, g2.x);
            atomicAdd(op + 5, g2.y);
            atomicAdd(op + 6, g3.x);
            atomicAdd(op + 7, g3.y);
        }
    }
}

// ---------------- launch ----------------
#define K2_DYN_SMEM (K2_WARPS * 2 * TILE_FLOATS * 4)   // 67584 bytes

extern "C" void kernel_launch(void* const* d_in, const int* in_sizes, int n_in,
                              void* d_out, int out_size)
{
    const float* z       = (const float*)d_in[0];
    const float* ctx     = (const float*)d_in[1];
    const float* noise   = (const float*)d_in[2];
    const float* conv_w  = (const float*)d_in[3];
    const float* conv_b  = (const float*)d_in[4];
    const float* Dm      = (const float*)d_in[5];
    const float* sigma_g = (const float*)d_in[6];
    const float* temp1   = (const float*)d_in[7];
    const float* W1      = (const float*)d_in[8];
    const float* b1      = (const float*)d_in[9];
    const float* W2      = (const float*)d_in[10];
    const float* b2      = (const float*)d_in[11];
    const float* temp2   = (const float*)d_in[12];
    const float* Amat    = (const float*)d_in[13];
    const float* Wx      = (const float*)d_in[14];
    const float* hmat    = (const float*)d_in[15];
    float* out = (float*)d_out;

    cudaFuncSetAttribute(k_attn, cudaFuncAttributeMaxDynamicSharedMemorySize, K2_DYN_SMEM);

    k_zero<<<(Mdim * Bdim / 4) / 256, 256>>>(out);
    k_attn<<<Bdim / K2_WARPS, 256, K2_DYN_SMEM>>>(ctx, z, noise, Dm, sigma_g,
                                                  conv_w, conv_b, temp1, W1, b1, W2, b2, temp2);
    k_mix<<<dim3(Bdim / K3_BT, Mdim / K3_MT, K3_SPLITS), K3_THREADS>>>(z, Wx, Amat, hmat, out);
}

// round 8
// speedup vs baseline: 1.0532x; 1.0532x over previous
#include <cuda_runtime.h>
#include <cstdint>
#include <cstddef>

#define Mdim 128
#define Ndim 64
#define Edim 32
#define Sdim 512
#define Bdim 8192

typedef unsigned long long ull;

// ---------------- scratch (no allocation allowed) ----------------
__device__ float g_zc[Bdim * Ndim];   // z_cur transposed: [b*64 + i]
__device__ float g_w [Bdim * Edim];   // expert weights:   [b*32 + e]

// ---------------- packed f32x2 helpers (sm_103a) ----------------
__device__ __forceinline__ void fma2(ull& acc, ull a, ull b)
{
    asm("fma.rn.f32x2 %0, %1, %2, %3;" : "=l"(acc) : "l"(a), "l"(b), "l"(acc));
}
__device__ __forceinline__ ull bcast2(float x)
{
    ull r;
    asm("mov.b64 %0, {%1, %1};" : "=l"(r) : "f"(x));
    return r;
}
__device__ __forceinline__ float2 unpack2(ull v)
{
    float2 f;
    asm("mov.b64 {%0, %1}, %2;" : "=f"(f.x), "=f"(f.y) : "l"(v));
    return f;
}

// ---------------- Kernel 1: z_cur = D @ z + sigma_g * noise (transposed out) ----------------
__global__ void k_zc(const float* __restrict__ z, const float* __restrict__ noise,
                     const float* __restrict__ Dm, const float* __restrict__ sigma_g)
{
    int b = blockIdx.x * blockDim.x + threadIdx.x;   // coalesced over b
    int i = blockIdx.y;                              // 0..63
    float acc = sigma_g[i] * noise[(size_t)i * Bdim + b];
    const float* drow = Dm + i * Mdim;
    #pragma unroll 8
    for (int m = 0; m < Mdim; ++m)
        acc = fmaf(drow[m], z[(size_t)m * Bdim + b], acc);
    g_zc[(size_t)b * Ndim + i] = acc;
}

// ---------------- Kernel 2: streaming online-softmax attention + conv-emb + MLP + expert softmax ----------------
#define K2_WARPS 8
#define CHUNK 8

struct OnlineState {
    float mrun, denom, pprev;
    float c0x, c0y, c1x, c1y;
};

__device__ __forceinline__ void row_proc(const float2 v, float zcx, float zcy,
                                         float invT1, OnlineState& st)
{
    float dd = fabsf(v.x - zcx) + fabsf(v.y - zcy);
    dd += __shfl_xor_sync(0xffffffffu, dd, 16);
    dd += __shfl_xor_sync(0xffffffffu, dd, 8);
    dd += __shfl_xor_sync(0xffffffffu, dd, 4);
    dd += __shfl_xor_sync(0xffffffffu, dd, 2);
    dd += __shfl_xor_sync(0xffffffffu, dd, 1);
    float logit = -dd * invT1;
    if (logit > st.mrun) {
        float s = __expf(st.mrun - logit);
        st.denom *= s; st.c0x *= s; st.c0y *= s; st.c1x *= s; st.c1y *= s; st.pprev *= s;
        st.mrun = logit;
    }
    float pw = __expf(logit - st.mrun);
    st.denom += pw;
    st.c0x = fmaf(pw, v.x, st.c0x);       st.c0y = fmaf(pw, v.y, st.c0y);
    st.c1x = fmaf(st.pprev, v.x, st.c1x); st.c1y = fmaf(st.pprev, v.y, st.c1y);
    st.pprev = pw;
}

__device__ __forceinline__ void load_chunk(float2* buf, const float2* p, size_t TSTEP, int cidx)
{
    const float2* q = p + (size_t)cidx * (size_t)CHUNK * TSTEP;
    #pragma unroll
    for (int r = 0; r < CHUNK; ++r) buf[r] = __ldcs(q + (size_t)r * TSTEP);
}

__device__ __forceinline__ void proc_chunk(const float2* buf, float zcx, float zcy,
                                           float invT1, OnlineState& st)
{
    #pragma unroll
    for (int r = 0; r < CHUNK; ++r) row_proc(buf[r], zcx, zcy, invT1, st);
}

__global__ __launch_bounds__(256, 4)
void k_attn(const float* __restrict__ ctx, const float* __restrict__ z,
            const float* __restrict__ conv_w, const float* __restrict__ conv_b,
            const float* __restrict__ temp1,
            const float* __restrict__ W1, const float* __restrict__ b1,
            const float* __restrict__ W2, const float* __restrict__ b2,
            const float* __restrict__ temp2)
{
    __shared__ float W1s[192 * 32];          // transposed [j][e]
    __shared__ float W2s[32 * 32];           // transposed [j][e]
    __shared__ float scomb[K2_WARPS][194];   // per-warp c0|c1 then emb|z (192 used)

    int tid = threadIdx.x;
    for (int t = tid; t < 192 * 32; t += 256) {
        int e = t / 192, j = t % 192;
        W1s[j * 32 + e] = W1[t];
    }
    for (int t = tid; t < 32 * 32; t += 256) {
        int e = t / 32, j = t % 32;
        W2s[j * 32 + e] = W2[t];
    }
    __syncthreads();

    int warp = tid >> 5, lane = tid & 31;
    int b = blockIdx.x * K2_WARPS + warp;

    float invT1 = 1.0f / fabsf(temp1[0]);
    float invT2 = 1.0f / fabsf(temp2[0]);

    float zcx = g_zc[(size_t)b * Ndim + 2 * lane];
    float zcy = g_zc[(size_t)b * Ndim + 2 * lane + 1];

    const float2* p = reinterpret_cast<const float2*>(ctx) + (size_t)b * (Ndim / 2) + lane;
    const size_t TSTEP = (size_t)Bdim * (Ndim / 2);  // float2 per seq step

    OnlineState st;
    st.mrun = -1e30f; st.denom = 0.f; st.pprev = 0.f;
    st.c0x = 0.f; st.c0y = 0.f; st.c1x = 0.f; st.c1y = 0.f;
    float2 buf0[CHUNK], buf1[CHUNK];

    load_chunk(buf0, p, TSTEP, 0);
    for (int cc = 0; cc < 62; cc += 2) {
        load_chunk(buf1, p, TSTEP, cc + 1);
        proc_chunk(buf0, zcx, zcy, invT1, st);
        load_chunk(buf0, p, TSTEP, cc + 2);
        proc_chunk(buf1, zcx, zcy, invT1, st);
    }
    load_chunk(buf1, p, TSTEP, 63);
    proc_chunk(buf0, zcx, zcy, invT1, st);   // chunk 62 (rows 496..503)
    // chunk 63: rows 504..510 normal, row 511 only feeds c1 (shifted tap)
    #pragma unroll
    for (int r = 0; r < CHUNK - 1; ++r) row_proc(buf1[r], zcx, zcy, invT1, st);
    {
        float2 v = buf1[CHUNK - 1];
        st.c1x = fmaf(st.pprev, v.x, st.c1x);
        st.c1y = fmaf(st.pprev, v.y, st.c1y);
    }

    float rinv = 1.0f / st.denom;
    float* sc = scomb[warp];
    sc[2 * lane]      = st.c0x * rinv;  sc[2 * lane + 1]      = st.c0y * rinv;
    sc[64 + 2 * lane] = st.c1x * rinv;  sc[64 + 2 * lane + 1] = st.c1y * rinv;
    __syncwarp();

    // emb[o] = conv_b[o] + sum_i cw0[o,i]*c0[i] + cw1[o,i]*c1[i]
    int o0 = 2 * lane, o1 = 2 * lane + 1;
    float e0 = conv_b[o0], e1 = conv_b[o1];
    const float* cwA = conv_w + (size_t)o0 * 128;   // conv_w[o][i][tap], stride 2 over i
    const float* cwB = conv_w + (size_t)o1 * 128;
    #pragma unroll 8
    for (int i = 0; i < 64; ++i) {
        float a = sc[i], c = sc[64 + i];
        e0 = fmaf(__ldg(cwA + 2 * i), a, e0);
        e0 = fmaf(__ldg(cwA + 2 * i + 1), c, e0);
        e1 = fmaf(__ldg(cwB + 2 * i), a, e1);
        e1 = fmaf(__ldg(cwB + 2 * i + 1), c, e1);
    }
    __syncwarp();
    sc[o0] = e0; sc[o1] = e1;                      // combined[0..63] = emb
    #pragma unroll
    for (int k = 0; k < 4; ++k) {
        int j = lane * 4 + k;
        sc[64 + j] = __ldg(z + (size_t)j * Bdim + b);  // combined[64..191] = z[:,b]
    }
    __syncwarp();

    // hidden[e] = relu(W1[e,:] . combined + b1[e]), lane == e
    float hs = b1[lane];
    #pragma unroll 8
    for (int j = 0; j < 192; ++j)
        hs = fmaf(W1s[j * 32 + lane], sc[j], hs);
    hs = fmaxf(hs, 0.f);

    float o2 = b2[lane];
    #pragma unroll
    for (int j = 0; j < 32; ++j)
        o2 = fmaf(W2s[j * 32 + lane], __shfl_sync(0xffffffffu, hs, j), o2);

    // expert softmax over lanes
    float lg = -o2 * invT2;
    float mx = lg;
    mx = fmaxf(mx, __shfl_xor_sync(0xffffffffu, mx, 16));
    mx = fmaxf(mx, __shfl_xor_sync(0xffffffffu, mx, 8));
    mx = fmaxf(mx, __shfl_xor_sync(0xffffffffu, mx, 4));
    mx = fmaxf(mx, __shfl_xor_sync(0xffffffffu, mx, 2));
    mx = fmaxf(mx, __shfl_xor_sync(0xffffffffu, mx, 1));
    float pw2 = __expf(lg - mx);
    float sm2 = pw2;
    sm2 += __shfl_xor_sync(0xffffffffu, sm2, 16);
    sm2 += __shfl_xor_sync(0xffffffffu, sm2, 8);
    sm2 += __shfl_xor_sync(0xffffffffu, sm2, 4);
    sm2 += __shfl_xor_sync(0xffffffffu, sm2, 2);
    sm2 += __shfl_xor_sync(0xffffffffu, sm2, 1);
    g_w[(size_t)b * 32 + lane] = pw2 / sm2;
}

// ---------------- Kernel 3: MoE mixture GEMM v3 ----------------
// out[m,b] = sum_{e,k} Wx[e,m,k]*w[e,b]*zcat[k,b] + z[m,b]*(A^T w)[m,b] + (h^T w)[m,b]
// A (=Wx rows) streamed global->regs (L2-resident, broadcast across tx lanes);
// V (=w*zcat) staged in double-buffered smem. No k-split, direct stores.
#define K3_BT 32
#define K3_MT 64
#define K3_THREADS 128

__global__ __launch_bounds__(K3_THREADS, 6)
void k_mix(const float* __restrict__ z, const float* __restrict__ Wx,
           const float* __restrict__ Amat, const float* __restrict__ hmat,
           float* __restrict__ out)
{
    __shared__ __align__(16) float Vs[2][32][40];   // [stage][k][b]  10.2 KB
    __shared__ __align__(16) float w_s[32][40];     // [e][b]          5.1 KB

    int tid = threadIdx.x;
    int b0 = blockIdx.x * K3_BT;
    int m0 = blockIdx.y * K3_MT;
    int tx = tid & 7;                    // 8 groups of 4 b
    int ty = tid >> 3;                   // 16 groups of 4 m
    int tx4 = tx * 4, ty4 = ty * 4;

    // ---- stage expert weights w_s[e][b] ----
    #pragma unroll
    for (int r = 0; r < 8; ++r) {
        int idx = tid + r * K3_THREADS;  // 0..1023
        int bb = idx >> 5, e = idx & 31;
        w_s[e][bb] = g_w[(size_t)(b0 + bb) * 32 + e];
    }
    __syncthreads();

    ull acc[4][2];                       // [m][b-pair]
    #pragma unroll
    for (int i = 0; i < 4; ++i) { acc[i][0] = 0ull; acc[i][1] = 0ull; }

    // ---- stage V chunk 0 (e=0, k0=0) ----
    #pragma unroll
    for (int r = 0; r < 2; ++r) {
        int q = tid + r * K3_THREADS;
        int kk = q >> 3, bq = (q & 7) * 4;
        float4 v = *reinterpret_cast<const float4*>(z + (size_t)kk * Bdim + b0 + bq);
        float4 wq = *reinterpret_cast<const float4*>(&w_s[0][bq]);
        v.x *= wq.x; v.y *= wq.y; v.z *= wq.z; v.w *= wq.w;
        *reinterpret_cast<float4*>(&Vs[0][kk][bq]) = v;
    }
    __syncthreads();

    float4 rV[2];
    for (int c = 0; c < 128; ++c) {
        int s = c & 1;
        int e = c >> 2, k0 = (c & 3) << 5;
        int en = 0, k0n = 0;

        // prefetch V for next chunk
        if (c < 127) {
            en = (c + 1) >> 2; k0n = ((c + 1) & 3) << 5;
            #pragma unroll
            for (int r = 0; r < 2; ++r) {
                int q = tid + r * K3_THREADS;
                int kk = q >> 3, bq = (q & 7) * 4;
                rV[r] = *reinterpret_cast<const float4*>(z + (size_t)(k0n + kk) * Bdim + b0 + bq);
            }
        }

        // ---- compute: A rows global->regs, double-buffered 4-kk groups ----
        const float* abase = Wx + (size_t)e * (Mdim * Mdim) + (size_t)(m0 + ty4) * Mdim + k0;
        float4 aw[2][4];
        #pragma unroll
        for (int i = 0; i < 4; ++i)
            aw[0][i] = *reinterpret_cast<const float4*>(abase + (size_t)i * Mdim);

        #pragma unroll
        for (int g = 0; g < 8; ++g) {
            if (g < 7) {
                #pragma unroll
                for (int i = 0; i < 4; ++i)
                    aw[(g + 1) & 1][i] = *reinterpret_cast<const float4*>(abase + (size_t)i * Mdim + (g + 1) * 4);
            }
            const float4* ag = aw[g & 1];
            #pragma unroll
            for (int j = 0; j < 4; ++j) {
                int kk = g * 4 + j;
                ulonglong2 va = *reinterpret_cast<const ulonglong2*>(&Vs[s][kk][tx4]);
                float a0 = (j == 0) ? ag[0].x : (j == 1) ? ag[0].y : (j == 2) ? ag[0].z : ag[0].w;
                float a1 = (j == 0) ? ag[1].x : (j == 1) ? ag[1].y : (j == 2) ? ag[1].z : ag[1].w;
                float a2 = (j == 0) ? ag[2].x : (j == 1) ? ag[2].y : (j == 2) ? ag[2].z : ag[2].w;
                float a3 = (j == 0) ? ag[3].x : (j == 1) ? ag[3].y : (j == 2) ? ag[3].z : ag[3].w;
                fma2(acc[0][0], bcast2(a0), va.x); fma2(acc[0][1], bcast2(a0), va.y);
                fma2(acc[1][0], bcast2(a1), va.x); fma2(acc[1][1], bcast2(a1), va.y);
                fma2(acc[2][0], bcast2(a2), va.x); fma2(acc[2][1], bcast2(a2), va.y);
                fma2(acc[3][0], bcast2(a3), va.x); fma2(acc[3][1], bcast2(a3), va.y);
            }
        }

        // ---- store staged V for next chunk ----
        if (c < 127) {
            int sn = (c + 1) & 1;
            #pragma unroll
            for (int r = 0; r < 2; ++r) {
                int q = tid + r * K3_THREADS;
                int kk = q >> 3, bq = (q & 7) * 4;
                int kg = k0n + kk;
                float4 v = rV[r];
                if (kg >= Mdim - 2) {
                    v.x = fmaxf(v.x, 0.f); v.y = fmaxf(v.y, 0.f);
                    v.z = fmaxf(v.z, 0.f); v.w = fmaxf(v.w, 0.f);
                }
                float4 wq = *reinterpret_cast<const float4*>(&w_s[en][bq]);
                v.x *= wq.x; v.y *= wq.y; v.z *= wq.z; v.w *= wq.w;
                *reinterpret_cast<float4*>(&Vs[sn][kk][bq]) = v;
            }
        }
        __syncthreads();
    }

    // ---- epilogue: h^T w and A^T w terms ----
    float hacc[4][4] = {};
    float aacc[4][4] = {};
    #pragma unroll 4
    for (int e = 0; e < 32; ++e) {
        float4 hv = *reinterpret_cast<const float4*>(hmat + (size_t)e * Mdim + m0 + ty4);
        float4 av = *reinterpret_cast<const float4*>(Amat + (size_t)e * Mdim + m0 + ty4);
        float4 wq = *reinterpret_cast<const float4*>(&w_s[e][tx4]);
        float wv[4] = {wq.x, wq.y, wq.z, wq.w};
        float hvv[4] = {hv.x, hv.y, hv.z, hv.w};
        float avv[4] = {av.x, av.y, av.z, av.w};
        #pragma unroll
        for (int i = 0; i < 4; ++i)
            #pragma unroll
            for (int j = 0; j < 4; ++j) {
                hacc[i][j] = fmaf(hvv[i], wv[j], hacc[i][j]);
                aacc[i][j] = fmaf(avv[i], wv[j], aacc[i][j]);
            }
    }

    // ---- write out = acc + h-term + z .* A-term ----
    #pragma unroll
    for (int i = 0; i < 4; ++i) {
        int m = m0 + ty4 + i;
        float2 g0 = unpack2(acc[i][0]);
        float2 g1 = unpack2(acc[i][1]);
        const float4 zv = *reinterpret_cast<const float4*>(z + (size_t)m * Bdim + b0 + tx4);
        float4 o4;
        o4.x = g0.x + hacc[i][0] + zv.x * aacc[i][0];
        o4.y = g0.y + hacc[i][1] + zv.y * aacc[i][1];
        o4.z = g1.x + hacc[i][2] + zv.z * aacc[i][2];
        o4.w = g1.y + hacc[i][3] + zv.w * aacc[i][3];
        *reinterpret_cast<float4*>(out + (size_t)m * Bdim + b0 + tx4) = o4;
    }
}

// ---------------- launch ----------------
extern "C" void kernel_launch(void* const* d_in, const int* in_sizes, int n_in,
                              void* d_out, int out_size)
{
    const float* z       = (const float*)d_in[0];
    const float* ctx     = (const float*)d_in[1];
    const float* noise   = (const float*)d_in[2];
    const float* conv_w  = (const float*)d_in[3];
    const float* conv_b  = (const float*)d_in[4];
    const float* Dm      = (const float*)d_in[5];
    const float* sigma_g = (const float*)d_in[6];
    const float* temp1   = (const float*)d_in[7];
    const float* W1      = (const float*)d_in[8];
    const float* b1      = (const float*)d_in[9];
    const float* W2      = (const float*)d_in[10];
    const float* b2      = (const float*)d_in[11];
    const float* temp2   = (const float*)d_in[12];
    const float* Amat    = (const float*)d_in[13];
    const float* Wx      = (const float*)d_in[14];
    const float* hmat    = (const float*)d_in[15];
    float* out = (float*)d_out;

    k_zc<<<dim3(Bdim / 256, Ndim), 256>>>(z, noise, Dm, sigma_g);
    k_attn<<<Bdim / K2_WARPS, 256>>>(ctx, z, conv_w, conv_b, temp1, W1, b1, W2, b2, temp2);
    k_mix<<<dim3(Bdim / K3_BT, Mdim / K3_MT), K3_THREADS>>>(z, Wx, Amat, hmat, out);
}

// round 13
// speedup vs baseline: 1.1778x; 1.1183x over previous
#include <cuda_runtime.h>
#include <cuda_bf16.h>
#include <cstdint>
#include <cstddef>

#define Mdim 128
#define Ndim 64
#define Edim 32
#define Sdim 512
#define Bdim 8192

typedef unsigned long long ull;

// ---------------- scratch (no allocation allowed) ----------------
__device__ float g_zc[Bdim * Ndim];                    // z_cur transposed: [b*64 + i]
__device__ float g_w [Bdim * Edim];                    // expert weights:   [b*32 + e]
__device__ __nv_bfloat16 g_wx_hi[Edim * Mdim * Mdim];  // Wx hi bf16 [e][m][k]
__device__ __nv_bfloat16 g_wx_lo[Edim * Mdim * Mdim];  // Wx lo bf16

// ---------------- Kernel C0: Wx -> bf16 hi/lo ----------------
__global__ void k_conv(const float* __restrict__ Wx)
{
    int idx = blockIdx.x * 256 + threadIdx.x;
    float v = Wx[idx];
    __nv_bfloat16 h = __float2bfloat16(v);
    g_wx_hi[idx] = h;
    g_wx_lo[idx] = __float2bfloat16(v - __bfloat162float(h));
}

// ---------------- Kernel 1: z_cur = D @ z + sigma_g * noise (transposed out) ----------------
__global__ void k_zc(const float* __restrict__ z, const float* __restrict__ noise,
                     const float* __restrict__ Dm, const float* __restrict__ sigma_g)
{
    int b = blockIdx.x * blockDim.x + threadIdx.x;
    int i = blockIdx.y;
    float acc = sigma_g[i] * noise[(size_t)i * Bdim + b];
    const float* drow = Dm + i * Mdim;
    #pragma unroll 8
    for (int m = 0; m < Mdim; ++m)
        acc = fmaf(drow[m], z[(size_t)m * Bdim + b], acc);
    g_zc[(size_t)b * Ndim + i] = acc;
}

// ---------------- Kernel 2: streaming online-softmax attention + conv-emb + MLP + expert softmax ----------------
#define K2_WARPS 8
#define CHUNK 8

struct OnlineState {
    float mrun, denom, pprev;
    float c0x, c0y, c1x, c1y;
};

__device__ __forceinline__ void row_proc(const float2 v, float zcx, float zcy,
                                         float invT1, OnlineState& st)
{
    float dd = fabsf(v.x - zcx) + fabsf(v.y - zcy);
    dd += __shfl_xor_sync(0xffffffffu, dd, 16);
    dd += __shfl_xor_sync(0xffffffffu, dd, 8);
    dd += __shfl_xor_sync(0xffffffffu, dd, 4);
    dd += __shfl_xor_sync(0xffffffffu, dd, 2);
    dd += __shfl_xor_sync(0xffffffffu, dd, 1);
    float logit = -dd * invT1;
    if (logit > st.mrun) {
        float s = __expf(st.mrun - logit);
        st.denom *= s; st.c0x *= s; st.c0y *= s; st.c1x *= s; st.c1y *= s; st.pprev *= s;
        st.mrun = logit;
    }
    float pw = __expf(logit - st.mrun);
    st.denom += pw;
    st.c0x = fmaf(pw, v.x, st.c0x);       st.c0y = fmaf(pw, v.y, st.c0y);
    st.c1x = fmaf(st.pprev, v.x, st.c1x); st.c1y = fmaf(st.pprev, v.y, st.c1y);
    st.pprev = pw;
}

__device__ __forceinline__ void load_chunk(float2* buf, const float2* p, size_t TSTEP, int cidx)
{
    const float2* q = p + (size_t)cidx * (size_t)CHUNK * TSTEP;
    #pragma unroll
    for (int r = 0; r < CHUNK; ++r) buf[r] = __ldcs(q + (size_t)r * TSTEP);
}

__device__ __forceinline__ void proc_chunk(const float2* buf, float zcx, float zcy,
                                           float invT1, OnlineState& st)
{
    #pragma unroll
    for (int r = 0; r < CHUNK; ++r) row_proc(buf[r], zcx, zcy, invT1, st);
}

__global__ __launch_bounds__(256, 4)
void k_attn(const float* __restrict__ ctx, const float* __restrict__ z,
            const float* __restrict__ conv_w, const float* __restrict__ conv_b,
            const float* __restrict__ temp1,
            const float* __restrict__ W1, const float* __restrict__ b1,
            const float* __restrict__ W2, const float* __restrict__ b2,
            const float* __restrict__ temp2)
{
    __shared__ float W1s[192 * 32];
    __shared__ float W2s[32 * 32];
    __shared__ float scomb[K2_WARPS][194];

    int tid = threadIdx.x;
    for (int t = tid; t < 192 * 32; t += 256) {
        int e = t / 192, j = t % 192;
        W1s[j * 32 + e] = W1[t];
    }
    for (int t = tid; t < 32 * 32; t += 256) {
        int e = t / 32, j = t % 32;
        W2s[j * 32 + e] = W2[t];
    }
    __syncthreads();

    int warp = tid >> 5, lane = tid & 31;
    int b = blockIdx.x * K2_WARPS + warp;

    float invT1 = 1.0f / fabsf(temp1[0]);
    float invT2 = 1.0f / fabsf(temp2[0]);

    float zcx = g_zc[(size_t)b * Ndim + 2 * lane];
    float zcy = g_zc[(size_t)b * Ndim + 2 * lane + 1];

    const float2* p = reinterpret_cast<const float2*>(ctx) + (size_t)b * (Ndim / 2) + lane;
    const size_t TSTEP = (size_t)Bdim * (Ndim / 2);

    OnlineState st;
    st.mrun = -1e30f; st.denom = 0.f; st.pprev = 0.f;
    st.c0x = 0.f; st.c0y = 0.f; st.c1x = 0.f; st.c1y = 0.f;
    float2 buf0[CHUNK], buf1[CHUNK];

    load_chunk(buf0, p, TSTEP, 0);
    for (int cc = 0; cc < 62; cc += 2) {
        load_chunk(buf1, p, TSTEP, cc + 1);
        proc_chunk(buf0, zcx, zcy, invT1, st);
        load_chunk(buf0, p, TSTEP, cc + 2);
        proc_chunk(buf1, zcx, zcy, invT1, st);
    }
    load_chunk(buf1, p, TSTEP, 63);
    proc_chunk(buf0, zcx, zcy, invT1, st);
    #pragma unroll
    for (int r = 0; r < CHUNK - 1; ++r) row_proc(buf1[r], zcx, zcy, invT1, st);
    {
        float2 v = buf1[CHUNK - 1];
        st.c1x = fmaf(st.pprev, v.x, st.c1x);
        st.c1y = fmaf(st.pprev, v.y, st.c1y);
    }

    float rinv = 1.0f / st.denom;
    float* sc = scomb[warp];
    sc[2 * lane]      = st.c0x * rinv;  sc[2 * lane + 1]      = st.c0y * rinv;
    sc[64 + 2 * lane] = st.c1x * rinv;  sc[64 + 2 * lane + 1] = st.c1y * rinv;
    __syncwarp();

    int o0 = 2 * lane, o1 = 2 * lane + 1;
    float e0 = conv_b[o0], e1 = conv_b[o1];
    const float* cwA = conv_w + (size_t)o0 * 128;
    const float* cwB = conv_w + (size_t)o1 * 128;
    #pragma unroll 8
    for (int i = 0; i < 64; ++i) {
        float a = sc[i], c = sc[64 + i];
        e0 = fmaf(__ldg(cwA + 2 * i), a, e0);
        e0 = fmaf(__ldg(cwA + 2 * i + 1), c, e0);
        e1 = fmaf(__ldg(cwB + 2 * i), a, e1);
        e1 = fmaf(__ldg(cwB + 2 * i + 1), c, e1);
    }
    __syncwarp();
    sc[o0] = e0; sc[o1] = e1;
    #pragma unroll
    for (int k = 0; k < 4; ++k) {
        int j = lane * 4 + k;
        sc[64 + j] = __ldg(z + (size_t)j * Bdim + b);
    }
    __syncwarp();

    float hs = b1[lane];
    #pragma unroll 8
    for (int j = 0; j < 192; ++j)
        hs = fmaf(W1s[j * 32 + lane], sc[j], hs);
    hs = fmaxf(hs, 0.f);

    float o2 = b2[lane];
    #pragma unroll
    for (int j = 0; j < 32; ++j)
        o2 = fmaf(W2s[j * 32 + lane], __shfl_sync(0xffffffffu, hs, j), o2);

    float lg = -o2 * invT2;
    float mx = lg;
    mx = fmaxf(mx, __shfl_xor_sync(0xffffffffu, mx, 16));
    mx = fmaxf(mx, __shfl_xor_sync(0xffffffffu, mx, 8));
    mx = fmaxf(mx, __shfl_xor_sync(0xffffffffu, mx, 4));
    mx = fmaxf(mx, __shfl_xor_sync(0xffffffffu, mx, 2));
    mx = fmaxf(mx, __shfl_xor_sync(0xffffffffu, mx, 1));
    float pw2 = __expf(lg - mx);
    float sm2 = pw2;
    sm2 += __shfl_xor_sync(0xffffffffu, sm2, 16);
    sm2 += __shfl_xor_sync(0xffffffffu, sm2, 8);
    sm2 += __shfl_xor_sync(0xffffffffu, sm2, 4);
    sm2 += __shfl_xor_sync(0xffffffffu, sm2, 2);
    sm2 += __shfl_xor_sync(0xffffffffu, sm2, 1);
    g_w[(size_t)b * 32 + lane] = pw2 / sm2;
}

// ---------------- Kernel 3: mma.sync bf16 hi/lo MoE mixture GEMM ----------------
// D1[m,b] = sum_{e,k} Wx[e,m,k]*(w[e,b]*zcat[k,b]) + sum_e h[e,m]w[e,b]
// D2[m,b] = sum_e A[e,m]w[e,b];   out = D1 + z .* D2
// bf16 hi/lo split, 3 products per step (hi*hi + hi*lo + lo*hi).
#define NB 64
#define APAD 40     // bf16 elems per smem A/V row (80 B, conflict-free frag loads)

__device__ __forceinline__ void mma_bf16(float* d, const uint32_t* a, const uint32_t* b)
{
    asm volatile(
        "mma.sync.aligned.m16n8k16.row.col.f32.bf16.bf16.f32 "
        "{%0,%1,%2,%3}, {%4,%5,%6,%7}, {%8,%9}, {%0,%1,%2,%3};"
        : "+f"(d[0]), "+f"(d[1]), "+f"(d[2]), "+f"(d[3])
        : "r"(a[0]), "r"(a[1]), "r"(a[2]), "r"(a[3]), "r"(b[0]), "r"(b[1]));
}

__global__ __launch_bounds__(256)
void k_mixm(const float* __restrict__ z, const float* __restrict__ Amat,
            const float* __restrict__ hmat, float* __restrict__ out)
{
    __shared__ __nv_bfloat16 As_hi[Mdim][APAD];   // [m][k32]  10.2 KB
    __shared__ __nv_bfloat16 As_lo[Mdim][APAD];
    __shared__ __nv_bfloat16 Vs_hi[NB][APAD];     // [b][k32]   5.1 KB
    __shared__ __nv_bfloat16 Vs_lo[NB][APAD];
    __shared__ float w_s[Edim][NB + 4];           //            8.7 KB

    int tid = threadIdx.x;
    int warp = tid >> 5, lane = tid & 31;
    int g = lane >> 2, t = lane & 3;
    int b0 = blockIdx.x * NB;
    int m_off = warp * 16;

    // stage w_s[e][b]
    #pragma unroll
    for (int r = 0; r < 8; ++r) {
        int idx = tid + r * 256;            // 0..2047
        int bb = idx >> 5, e = idx & 31;
        w_s[e][bb] = g_w[(size_t)(b0 + bb) * 32 + e];
    }

    float D1[8][4], D2[8][4];
    #pragma unroll
    for (int nt = 0; nt < 8; ++nt)
        #pragma unroll
        for (int j = 0; j < 4; ++j) { D1[nt][j] = 0.f; D2[nt][j] = 0.f; }

    for (int c = 0; c < 130; ++c) {
        __syncthreads();
        if (c < 128) {
            int e = c >> 2, k0 = (c & 3) << 5;
            // A tile: [128 m][32 k] bf16 hi/lo from preconverted Wx (8B loads)
            // row stride = 128 bf16 = 32 ull
            const ull* ghi = reinterpret_cast<const ull*>(g_wx_hi + (e << 14) + k0);
            const ull* glo = reinterpret_cast<const ull*>(g_wx_lo + (e << 14) + k0);
            #pragma unroll
            for (int r = 0; r < 4; ++r) {
                int idx = tid + (r << 8);       // 0..1023
                int m = idx >> 3, q = idx & 7;  // 8 x 8B per row
                ull vh = ghi[(m << 5) + q];
                ull vl = glo[(m << 5) + q];
                *reinterpret_cast<ull*>(&As_hi[m][q << 2]) = vh;
                *reinterpret_cast<ull*>(&As_lo[m][q << 2]) = vl;
            }
            // V tile: [64 b][32 k] = w[e,b]*zcat[k,b], hi/lo
            #pragma unroll
            for (int r = 0; r < 2; ++r) {
                int idx = tid + (r << 8);       // 0..511
                int kk = idx >> 4, bq = (idx & 15) << 2;
                int kl = k0 + kk;
                float4 v = *reinterpret_cast<const float4*>(z + (size_t)kl * Bdim + b0 + bq);
                if (kl >= Mdim - 2) {
                    v.x = fmaxf(v.x, 0.f); v.y = fmaxf(v.y, 0.f);
                    v.z = fmaxf(v.z, 0.f); v.w = fmaxf(v.w, 0.f);
                }
                float vv[4] = {v.x * w_s[e][bq], v.y * w_s[e][bq + 1],
                               v.z * w_s[e][bq + 2], v.w * w_s[e][bq + 3]};
                #pragma unroll
                for (int i = 0; i < 4; ++i) {
                    __nv_bfloat16 hh = __float2bfloat16(vv[i]);
                    Vs_hi[bq + i][kk] = hh;
                    Vs_lo[bq + i][kk] = __float2bfloat16(vv[i] - __bfloat162float(hh));
                }
            }
        } else {
            // A tile: [128 m][32 e] = (h or A)^T, hi/lo
            const float* src = (c == 128) ? hmat : Amat;
            #pragma unroll
            for (int r = 0; r < 16; ++r) {
                int idx = tid + (r << 8);       // 0..4095
                int e2 = idx >> 7, m = idx & 127;
                float v = src[idx];
                __nv_bfloat16 hh = __float2bfloat16(v);
                As_hi[m][e2] = hh;
                As_lo[m][e2] = __float2bfloat16(v - __bfloat162float(hh));
            }
            // V tile (once): [64 b][32 e] = w, hi/lo
            if (c == 128) {
                #pragma unroll
                for (int r = 0; r < 8; ++r) {
                    int idx = tid + (r << 8);   // 0..2047
                    int bb = idx >> 5, e2 = idx & 31;
                    float v = w_s[e2][bb];
                    __nv_bfloat16 hh = __float2bfloat16(v);
                    Vs_hi[bb][e2] = hh;
                    Vs_lo[bb][e2] = __float2bfloat16(v - __bfloat162float(hh));
                }
            }
        }
        __syncthreads();

        float (*D)[4] = (c == 129) ? D2 : D1;
        #pragma unroll
        for (int s = 0; s < 2; ++s) {
            int kb = s << 4;
            uint32_t ah[4], al[4];
            ah[0] = *reinterpret_cast<const uint32_t*>(&As_hi[m_off + g][kb + 2 * t]);
            ah[1] = *reinterpret_cast<const uint32_t*>(&As_hi[m_off + g + 8][kb + 2 * t]);
            ah[2] = *reinterpret_cast<const uint32_t*>(&As_hi[m_off + g][kb + 2 * t + 8]);
            ah[3] = *reinterpret_cast<const uint32_t*>(&As_hi[m_off + g + 8][kb + 2 * t + 8]);
            al[0] = *reinterpret_cast<const uint32_t*>(&As_lo[m_off + g][kb + 2 * t]);
            al[1] = *reinterpret_cast<const uint32_t*>(&As_lo[m_off + g + 8][kb + 2 * t]);
            al[2] = *reinterpret_cast<const uint32_t*>(&As_lo[m_off + g][kb + 2 * t + 8]);
            al[3] = *reinterpret_cast<const uint32_t*>(&As_lo[m_off + g + 8][kb + 2 * t + 8]);
            #pragma unroll
            for (int nt = 0; nt < 8; ++nt) {
                uint32_t bh[2], bl[2];
                bh[0] = *reinterpret_cast<const uint32_t*>(&Vs_hi[(nt << 3) + g][kb + 2 * t]);
                bh[1] = *reinterpret_cast<const uint32_t*>(&Vs_hi[(nt << 3) + g][kb + 2 * t + 8]);
                bl[0] = *reinterpret_cast<const uint32_t*>(&Vs_lo[(nt << 3) + g][kb + 2 * t]);
                bl[1] = *reinterpret_cast<const uint32_t*>(&Vs_lo[(nt << 3) + g][kb + 2 * t + 8]);
                mma_bf16(D[nt], ah, bh);
                mma_bf16(D[nt], ah, bl);
                mma_bf16(D[nt], al, bh);
            }
        }
    }

    // epilogue: out = D1 + z .* D2
    #pragma unroll
    for (int nt = 0; nt < 8; ++nt) {
        int cb = b0 + (nt << 3) + 2 * t;
        int m0r = m_off + g, m1r = m_off + g + 8;
        float2 z0 = *reinterpret_cast<const float2*>(z + (size_t)m0r * Bdim + cb);
        float2 z1 = *reinterpret_cast<const float2*>(z + (size_t)m1r * Bdim + cb);
        float2 o0, o1;
        o0.x = D1[nt][0] + z0.x * D2[nt][0];
        o0.y = D1[nt][1] + z0.y * D2[nt][1];
        o1.x = D1[nt][2] + z1.x * D2[nt][2];
        o1.y = D1[nt][3] + z1.y * D2[nt][3];
        *reinterpret_cast<float2*>(out + (size_t)m0r * Bdim + cb) = o0;
        *reinterpret_cast<float2*>(out + (size_t)m1r * Bdim + cb) = o1;
    }
}

// ---------------- launch ----------------
extern "C" void kernel_launch(void* const* d_in, const int* in_sizes, int n_in,
                              void* d_out, int out_size)
{
    const float* z       = (const float*)d_in[0];
    const float* ctx     = (const float*)d_in[1];
    const float* noise   = (const float*)d_in[2];
    const float* conv_w  = (const float*)d_in[3];
    const float* conv_b  = (const float*)d_in[4];
    const float* Dm      = (const float*)d_in[5];
    const float* sigma_g = (const float*)d_in[6];
    const float* temp1   = (const float*)d_in[7];
    const float* W1      = (const float*)d_in[8];
    const float* b1      = (const float*)d_in[9];
    const float* W2      = (const float*)d_in[10];
    const float* b2      = (const float*)d_in[11];
    const float* temp2   = (const float*)d_in[12];
    const float* Amat    = (const float*)d_in[13];
    const float* Wx      = (const float*)d_in[14];
    const float* hmat    = (const float*)d_in[15];
    float* out = (float*)d_out;

    k_conv<<<(Edim * Mdim * Mdim) / 256, 256>>>(Wx);
    k_zc<<<dim3(Bdim / 256, Ndim), 256>>>(z, noise, Dm, sigma_g);
    k_attn<<<Bdim / K2_WARPS, 256>>>(ctx, z, conv_w, conv_b, temp1, W1, b1, W2, b2, temp2);
    k_mixm<<<Bdim / NB, 256>>>(z, Amat, hmat, out);
}

// round 14
// speedup vs baseline: 1.2138x; 1.0306x over previous
#include <cuda_runtime.h>
#include <cuda_bf16.h>
#include <cstdint>
#include <cstddef>

#define Mdim 128
#define Ndim 64
#define Edim 32
#define Sdim 512
#define Bdim 8192

typedef unsigned long long ull;

// ---------------- scratch (no allocation allowed) ----------------
__device__ float g_zc[Bdim * Ndim];                    // z_cur transposed: [b*64 + i]
__device__ float g_w [Bdim * Edim];                    // expert weights:   [b*32 + e]
__device__ __nv_bfloat16 g_wx_hi[Edim * Mdim * Mdim];  // Wx hi bf16 [e][m][k]
__device__ __nv_bfloat16 g_wx_lo[Edim * Mdim * Mdim];  // Wx lo bf16

// ---------------- Kernel C0: Wx -> bf16 hi/lo ----------------
__global__ void k_conv(const float* __restrict__ Wx)
{
    int idx = blockIdx.x * 256 + threadIdx.x;
    float v = Wx[idx];
    __nv_bfloat16 h = __float2bfloat16(v);
    g_wx_hi[idx] = h;
    g_wx_lo[idx] = __float2bfloat16(v - __bfloat162float(h));
}

// ---------------- Kernel 1: z_cur = D @ z + sigma_g * noise (transposed out) ----------------
__global__ void k_zc(const float* __restrict__ z, const float* __restrict__ noise,
                     const float* __restrict__ Dm, const float* __restrict__ sigma_g)
{
    int b = blockIdx.x * blockDim.x + threadIdx.x;
    int i = blockIdx.y;
    float acc = sigma_g[i] * noise[(size_t)i * Bdim + b];
    const float* drow = Dm + i * Mdim;
    #pragma unroll 8
    for (int m = 0; m < Mdim; ++m)
        acc = fmaf(drow[m], z[(size_t)m * Bdim + b], acc);
    g_zc[(size_t)b * Ndim + i] = acc;
}

// ---------------- Kernel 2: streaming online-softmax attention + conv-emb + MLP + expert softmax ----------------
#define K2_WARPS 8
#define CHUNK 8

struct OnlineState {
    float mrun, denom, pprev;
    float c0x, c0y, c1x, c1y;
};

__device__ __forceinline__ void row_proc(const float2 v, float zcx, float zcy,
                                         float invT1, OnlineState& st)
{
    float dd = fabsf(v.x - zcx) + fabsf(v.y - zcy);
    dd += __shfl_xor_sync(0xffffffffu, dd, 16);
    dd += __shfl_xor_sync(0xffffffffu, dd, 8);
    dd += __shfl_xor_sync(0xffffffffu, dd, 4);
    dd += __shfl_xor_sync(0xffffffffu, dd, 2);
    dd += __shfl_xor_sync(0xffffffffu, dd, 1);
    float logit = -dd * invT1;
    if (logit > st.mrun) {
        float s = __expf(st.mrun - logit);
        st.denom *= s; st.c0x *= s; st.c0y *= s; st.c1x *= s; st.c1y *= s; st.pprev *= s;
        st.mrun = logit;
    }
    float pw = __expf(logit - st.mrun);
    st.denom += pw;
    st.c0x = fmaf(pw, v.x, st.c0x);       st.c0y = fmaf(pw, v.y, st.c0y);
    st.c1x = fmaf(st.pprev, v.x, st.c1x); st.c1y = fmaf(st.pprev, v.y, st.c1y);
    st.pprev = pw;
}

__device__ __forceinline__ void load_chunk(float2* buf, const float2* p, size_t TSTEP, int cidx)
{
    const float2* q = p + (size_t)cidx * (size_t)CHUNK * TSTEP;
    #pragma unroll
    for (int r = 0; r < CHUNK; ++r) buf[r] = __ldcs(q + (size_t)r * TSTEP);
}

__device__ __forceinline__ void proc_chunk(const float2* buf, float zcx, float zcy,
                                           float invT1, OnlineState& st)
{
    #pragma unroll
    for (int r = 0; r < CHUNK; ++r) row_proc(buf[r], zcx, zcy, invT1, st);
}

__global__ __launch_bounds__(256, 4)
void k_attn(const float* __restrict__ ctx, const float* __restrict__ z,
            const float* __restrict__ conv_w, const float* __restrict__ conv_b,
            const float* __restrict__ temp1,
            const float* __restrict__ W1, const float* __restrict__ b1,
            const float* __restrict__ W2, const float* __restrict__ b2,
            const float* __restrict__ temp2)
{
    __shared__ float W1s[192 * 32];
    __shared__ float W2s[32 * 32];
    __shared__ float scomb[K2_WARPS][194];

    int tid = threadIdx.x;
    for (int t = tid; t < 192 * 32; t += 256) {
        int e = t / 192, j = t % 192;
        W1s[j * 32 + e] = W1[t];
    }
    for (int t = tid; t < 32 * 32; t += 256) {
        int e = t / 32, j = t % 32;
        W2s[j * 32 + e] = W2[t];
    }
    __syncthreads();

    int warp = tid >> 5, lane = tid & 31;
    int b = blockIdx.x * K2_WARPS + warp;

    float invT1 = 1.0f / fabsf(temp1[0]);
    float invT2 = 1.0f / fabsf(temp2[0]);

    float zcx = g_zc[(size_t)b * Ndim + 2 * lane];
    float zcy = g_zc[(size_t)b * Ndim + 2 * lane + 1];

    const float2* p = reinterpret_cast<const float2*>(ctx) + (size_t)b * (Ndim / 2) + lane;
    const size_t TSTEP = (size_t)Bdim * (Ndim / 2);

    OnlineState st;
    st.mrun = -1e30f; st.denom = 0.f; st.pprev = 0.f;
    st.c0x = 0.f; st.c0y = 0.f; st.c1x = 0.f; st.c1y = 0.f;
    float2 buf0[CHUNK], buf1[CHUNK];

    load_chunk(buf0, p, TSTEP, 0);
    for (int cc = 0; cc < 62; cc += 2) {
        load_chunk(buf1, p, TSTEP, cc + 1);
        proc_chunk(buf0, zcx, zcy, invT1, st);
        load_chunk(buf0, p, TSTEP, cc + 2);
        proc_chunk(buf1, zcx, zcy, invT1, st);
    }
    load_chunk(buf1, p, TSTEP, 63);
    proc_chunk(buf0, zcx, zcy, invT1, st);
    #pragma unroll
    for (int r = 0; r < CHUNK - 1; ++r) row_proc(buf1[r], zcx, zcy, invT1, st);
    {
        float2 v = buf1[CHUNK - 1];
        st.c1x = fmaf(st.pprev, v.x, st.c1x);
        st.c1y = fmaf(st.pprev, v.y, st.c1y);
    }

    float rinv = 1.0f / st.denom;
    float* sc = scomb[warp];
    sc[2 * lane]      = st.c0x * rinv;  sc[2 * lane + 1]      = st.c0y * rinv;
    sc[64 + 2 * lane] = st.c1x * rinv;  sc[64 + 2 * lane + 1] = st.c1y * rinv;
    __syncwarp();

    int o0 = 2 * lane, o1 = 2 * lane + 1;
    float e0 = conv_b[o0], e1 = conv_b[o1];
    const float* cwA = conv_w + (size_t)o0 * 128;
    const float* cwB = conv_w + (size_t)o1 * 128;
    #pragma unroll 8
    for (int i = 0; i < 64; ++i) {
        float a = sc[i], c = sc[64 + i];
        e0 = fmaf(__ldg(cwA + 2 * i), a, e0);
        e0 = fmaf(__ldg(cwA + 2 * i + 1), c, e0);
        e1 = fmaf(__ldg(cwB + 2 * i), a, e1);
        e1 = fmaf(__ldg(cwB + 2 * i + 1), c, e1);
    }
    __syncwarp();
    sc[o0] = e0; sc[o1] = e1;
    #pragma unroll
    for (int k = 0; k < 4; ++k) {
        int j = lane * 4 + k;
        sc[64 + j] = __ldg(z + (size_t)j * Bdim + b);
    }
    __syncwarp();

    float hs = b1[lane];
    #pragma unroll 8
    for (int j = 0; j < 192; ++j)
        hs = fmaf(W1s[j * 32 + lane], sc[j], hs);
    hs = fmaxf(hs, 0.f);

    float o2 = b2[lane];
    #pragma unroll
    for (int j = 0; j < 32; ++j)
        o2 = fmaf(W2s[j * 32 + lane], __shfl_sync(0xffffffffu, hs, j), o2);

    float lg = -o2 * invT2;
    float mx = lg;
    mx = fmaxf(mx, __shfl_xor_sync(0xffffffffu, mx, 16));
    mx = fmaxf(mx, __shfl_xor_sync(0xffffffffu, mx, 8));
    mx = fmaxf(mx, __shfl_xor_sync(0xffffffffu, mx, 4));
    mx = fmaxf(mx, __shfl_xor_sync(0xffffffffu, mx, 2));
    mx = fmaxf(mx, __shfl_xor_sync(0xffffffffu, mx, 1));
    float pw2 = __expf(lg - mx);
    float sm2 = pw2;
    sm2 += __shfl_xor_sync(0xffffffffu, sm2, 16);
    sm2 += __shfl_xor_sync(0xffffffffu, sm2, 8);
    sm2 += __shfl_xor_sync(0xffffffffu, sm2, 4);
    sm2 += __shfl_xor_sync(0xffffffffu, sm2, 2);
    sm2 += __shfl_xor_sync(0xffffffffu, sm2, 1);
    g_w[(size_t)b * 32 + lane] = pw2 / sm2;
}

// ---------------- Kernel 3: mma.sync bf16 hi/lo MoE mixture GEMM (NB=32, occ 2) ----------------
// D1[m,b] = sum_{e,k} Wx[e,m,k]*(w[e,b]*zcat[k,b]) + sum_e h[e,m]w[e,b]
// D2[m,b] = sum_e A[e,m]w[e,b];   out = D1 + z .* D2
#define NB 32
#define NTILES_N (NB / 8)
#define APAD 40     // bf16 elems per smem A/V row (80 B, conflict-free frag loads)

__device__ __forceinline__ void mma_bf16(float* d, const uint32_t* a, const uint32_t* b)
{
    asm volatile(
        "mma.sync.aligned.m16n8k16.row.col.f32.bf16.bf16.f32 "
        "{%0,%1,%2,%3}, {%4,%5,%6,%7}, {%8,%9}, {%0,%1,%2,%3};"
        : "+f"(d[0]), "+f"(d[1]), "+f"(d[2]), "+f"(d[3])
        : "r"(a[0]), "r"(a[1]), "r"(a[2]), "r"(a[3]), "r"(b[0]), "r"(b[1]));
}

__global__ __launch_bounds__(256, 2)
void k_mixm(const float* __restrict__ z, const float* __restrict__ Amat,
            const float* __restrict__ hmat, float* __restrict__ out)
{
    __shared__ __nv_bfloat16 As_hi[Mdim][APAD];   // [m][k32]  10.2 KB
    __shared__ __nv_bfloat16 As_lo[Mdim][APAD];
    __shared__ __nv_bfloat16 Vs_hi[NB][APAD];     // [b][k32]   2.6 KB
    __shared__ __nv_bfloat16 Vs_lo[NB][APAD];
    __shared__ float w_s[Edim][NB + 4];           //            4.6 KB

    int tid = threadIdx.x;
    int warp = tid >> 5, lane = tid & 31;
    int g = lane >> 2, t = lane & 3;
    int b0 = blockIdx.x * NB;
    int m_off = warp * 16;

    // stage w_s[e][b]: 32e x 32b = 1024
    #pragma unroll
    for (int r = 0; r < 4; ++r) {
        int idx = tid + r * 256;
        int bb = idx >> 5, e = idx & 31;
        w_s[e][bb] = g_w[(size_t)(b0 + bb) * 32 + e];
    }

    float D1[NTILES_N][4], D2[NTILES_N][4];
    #pragma unroll
    for (int nt = 0; nt < NTILES_N; ++nt)
        #pragma unroll
        for (int j = 0; j < 4; ++j) { D1[nt][j] = 0.f; D2[nt][j] = 0.f; }

    for (int c = 0; c < 130; ++c) {
        __syncthreads();
        if (c < 128) {
            int e = c >> 2, k0 = (c & 3) << 5;
            // A tile: [128 m][32 k] bf16 hi/lo (8B loads, row stride 32 ull)
            const ull* ghi = reinterpret_cast<const ull*>(g_wx_hi + (e << 14) + k0);
            const ull* glo = reinterpret_cast<const ull*>(g_wx_lo + (e << 14) + k0);
            #pragma unroll
            for (int r = 0; r < 4; ++r) {
                int idx = tid + (r << 8);       // 0..1023
                int m = idx >> 3, q = idx & 7;  // 8 x 8B per row
                ull vh = ghi[(m << 5) + q];
                ull vl = glo[(m << 5) + q];
                *reinterpret_cast<ull*>(&As_hi[m][q << 2]) = vh;
                *reinterpret_cast<ull*>(&As_lo[m][q << 2]) = vl;
            }
            // V tile: [32 b][32 k] = w[e,b]*zcat[k,b], hi/lo (256 threads cover it)
            {
                int kk = tid >> 3, bq = (tid & 7) << 2;
                int kl = k0 + kk;
                float4 v = *reinterpret_cast<const float4*>(z + (size_t)kl * Bdim + b0 + bq);
                if (kl >= Mdim - 2) {
                    v.x = fmaxf(v.x, 0.f); v.y = fmaxf(v.y, 0.f);
                    v.z = fmaxf(v.z, 0.f); v.w = fmaxf(v.w, 0.f);
                }
                float vv[4] = {v.x * w_s[e][bq], v.y * w_s[e][bq + 1],
                               v.z * w_s[e][bq + 2], v.w * w_s[e][bq + 3]};
                #pragma unroll
                for (int i = 0; i < 4; ++i) {
                    __nv_bfloat16 hh = __float2bfloat16(vv[i]);
                    Vs_hi[bq + i][kk] = hh;
                    Vs_lo[bq + i][kk] = __float2bfloat16(vv[i] - __bfloat162float(hh));
                }
            }
        } else {
            // A tile: [128 m][32 e] = (h or A)^T, hi/lo
            const float* src = (c == 128) ? hmat : Amat;
            #pragma unroll
            for (int r = 0; r < 16; ++r) {
                int idx = tid + (r << 8);       // 0..4095
                int e2 = idx >> 7, m = idx & 127;
                float v = src[idx];
                __nv_bfloat16 hh = __float2bfloat16(v);
                As_hi[m][e2] = hh;
                As_lo[m][e2] = __float2bfloat16(v - __bfloat162float(hh));
            }
            // V tile (once): [32 b][32 e] = w, hi/lo
            if (c == 128) {
                #pragma unroll
                for (int r = 0; r < 4; ++r) {
                    int idx = tid + (r << 8);   // 0..1023
                    int bb = idx >> 5, e2 = idx & 31;
                    float v = w_s[e2][bb];
                    __nv_bfloat16 hh = __float2bfloat16(v);
                    Vs_hi[bb][e2] = hh;
                    Vs_lo[bb][e2] = __float2bfloat16(v - __bfloat162float(hh));
                }
            }
        }
        __syncthreads();

        float (*D)[4] = (c == 129) ? D2 : D1;
        #pragma unroll
        for (int s = 0; s < 2; ++s) {
            int kb = s << 4;
            uint32_t ah[4], al[4];
            ah[0] = *reinterpret_cast<const uint32_t*>(&As_hi[m_off + g][kb + 2 * t]);
            ah[1] = *reinterpret_cast<const uint32_t*>(&As_hi[m_off + g + 8][kb + 2 * t]);
            ah[2] = *reinterpret_cast<const uint32_t*>(&As_hi[m_off + g][kb + 2 * t + 8]);
            ah[3] = *reinterpret_cast<const uint32_t*>(&As_hi[m_off + g + 8][kb + 2 * t + 8]);
            al[0] = *reinterpret_cast<const uint32_t*>(&As_lo[m_off + g][kb + 2 * t]);
            al[1] = *reinterpret_cast<const uint32_t*>(&As_lo[m_off + g + 8][kb + 2 * t]);
            al[2] = *reinterpret_cast<const uint32_t*>(&As_lo[m_off + g][kb + 2 * t + 8]);
            al[3] = *reinterpret_cast<const uint32_t*>(&As_lo[m_off + g + 8][kb + 2 * t + 8]);
            #pragma unroll
            for (int nt = 0; nt < NTILES_N; ++nt) {
                uint32_t bh[2], bl[2];
                bh[0] = *reinterpret_cast<const uint32_t*>(&Vs_hi[(nt << 3) + g][kb + 2 * t]);
                bh[1] = *reinterpret_cast<const uint32_t*>(&Vs_hi[(nt << 3) + g][kb + 2 * t + 8]);
                bl[0] = *reinterpret_cast<const uint32_t*>(&Vs_lo[(nt << 3) + g][kb + 2 * t]);
                bl[1] = *reinterpret_cast<const uint32_t*>(&Vs_lo[(nt << 3) + g][kb + 2 * t + 8]);
                mma_bf16(D[nt], ah, bh);
                mma_bf16(D[nt], ah, bl);
                mma_bf16(D[nt], al, bh);
            }
        }
    }

    // epilogue: out = D1 + z .* D2
    #pragma unroll
    for (int nt = 0; nt < NTILES_N; ++nt) {
        int cb = b0 + (nt << 3) + 2 * t;
        int m0r = m_off + g, m1r = m_off + g + 8;
        float2 z0 = *reinterpret_cast<const float2*>(z + (size_t)m0r * Bdim + cb);
        float2 z1 = *reinterpret_cast<const float2*>(z + (size_t)m1r * Bdim + cb);
        float2 o0, o1;
        o0.x = D1[nt][0] + z0.x * D2[nt][0];
        o0.y = D1[nt][1] + z0.y * D2[nt][1];
        o1.x = D1[nt][2] + z1.x * D2[nt][2];
        o1.y = D1[nt][3] + z1.y * D2[nt][3];
        *reinterpret_cast<float2*>(out + (size_t)m0r * Bdim + cb) = o0;
        *reinterpret_cast<float2*>(out + (size_t)m1r * Bdim + cb) = o1;
    }
}

// ---------------- launch ----------------
extern "C" void kernel_launch(void* const* d_in, const int* in_sizes, int n_in,
                              void* d_out, int out_size)
{
    const float* z       = (const float*)d_in[0];
    const float* ctx     = (const float*)d_in[1];
    const float* noise   = (const float*)d_in[2];
    const float* conv_w  = (const float*)d_in[3];
    const float* conv_b  = (const float*)d_in[4];
    const float* Dm      = (const float*)d_in[5];
    const float* sigma_g = (const float*)d_in[6];
    const float* temp1   = (const float*)d_in[7];
    const float* W1      = (const float*)d_in[8];
    const float* b1      = (const float*)d_in[9];
    const float* W2      = (const float*)d_in[10];
    const float* b2      = (const float*)d_in[11];
    const float* temp2   = (const float*)d_in[12];
    const float* Amat    = (const float*)d_in[13];
    const float* Wx      = (const float*)d_in[14];
    const float* hmat    = (const float*)d_in[15];
    float* out = (float*)d_out;

    k_conv<<<(Edim * Mdim * Mdim) / 256, 256>>>(Wx);
    k_zc<<<dim3(Bdim / 256, Ndim), 256>>>(z, noise, Dm, sigma_g);
    k_attn<<<Bdim / K2_WARPS, 256>>>(ctx, z, conv_w, conv_b, temp1, W1, b1, W2, b2, temp2);
    k_mixm<<<Bdim / NB, 256>>>(z, Amat, hmat, out);
}